// round 12
// baseline (speedup 1.0000x reference)
#include <cuda_runtime.h>
#include <cuda_fp16.h>

#define NMAX 100000
#define EMAX 1600000
#define HIDD 64
#define FIN  128

__device__ int     g_cnt[NMAX];
__device__ int     g_off[NMAX + 1];
__device__ int     g_cur[NMAX];
__device__ int     g_esrc[EMAX];
__device__ int     g_eidx[EMAX];
__device__ int     g_bsum[512];
__device__ float   g_dinv[NMAX];
__device__ __half2 g_hl2 [NMAX * HIDD / 2];  // layer-1 linear, pre-scaled by dinv[src]
__device__ __half2 g_hl2b[NMAX * HIDD / 2];  // layer-2 linear, pre-scaled
__device__ __half2 g_ab2[NMAX * HIDD];       // [A|B] table
__device__ __half  g_w1h[FIN * HIDD];
__device__ __half  g_w2h[HIDD * HIDD];
__device__ __half  g_wabh[HIDD * 2 * HIDD];

static cudaStream_t g_s2;
static cudaEvent_t g_evFork, g_evDinv, g_evJoin;
namespace { struct StreamInit {
    StreamInit() {
        cudaStreamCreateWithFlags(&g_s2, cudaStreamNonBlocking);
        cudaEventCreateWithFlags(&g_evFork, cudaEventDisableTiming);
        cudaEventCreateWithFlags(&g_evDinv, cudaEventDisableTiming);
        cudaEventCreateWithFlags(&g_evJoin, cudaEventDisableTiming);
    }
} g_streamInit; }

// ---------------- CSC build ----------------
__global__ void count_in(const int* __restrict__ col, int* __restrict__ cnt, int E) {
    int e = blockIdx.x * blockDim.x + threadIdx.x;
    if (e < E) atomicAdd(&cnt[col[e]], 1);
}
__global__ void scan1(const int* __restrict__ cnt, int* __restrict__ off,
                      int* __restrict__ bsum, float* __restrict__ dinv, int n) {
    __shared__ int s[256];
    int tid = threadIdx.x;
    int i = blockIdx.x * 256 + tid;
    int v = (i < n) ? cnt[i] : 0;
    if (i < n) dinv[i] = rsqrtf((float)v + 1.0f);
    s[tid] = v;
    __syncthreads();
#pragma unroll
    for (int d = 1; d < 256; d <<= 1) {
        int t = (tid >= d) ? s[tid - d] : 0;
        __syncthreads();
        s[tid] += t;
        __syncthreads();
    }
    if (i < n) off[i] = s[tid] - v;
    if (tid == 255) bsum[blockIdx.x] = s[255];
}
__global__ void scan2(int* __restrict__ bsum, int nb) {
    __shared__ int s[512];
    int tid = threadIdx.x;
    int v = (tid < nb) ? bsum[tid] : 0;
    s[tid] = v;
    __syncthreads();
#pragma unroll
    for (int d = 1; d < 512; d <<= 1) {
        int t = (tid >= d) ? s[tid - d] : 0;
        __syncthreads();
        s[tid] += t;
        __syncthreads();
    }
    if (tid < nb) bsum[tid] = s[tid] - v;
}
__global__ void scan3(int* __restrict__ off, const int* __restrict__ bsum,
                      int* __restrict__ cur, int n, int E) {
    int i = blockIdx.x * 256 + threadIdx.x;
    if (i < n) {
        int o = off[i] + bsum[blockIdx.x];
        off[i] = o;
        cur[i] = o;
    }
    if (i == 0) off[n] = E;
}
__global__ void fill_csr(const int* __restrict__ row, const int* __restrict__ col,
                         int* __restrict__ cur, int* __restrict__ esrc,
                         int* __restrict__ eidx, int E) {
    int e = blockIdx.x * blockDim.x + threadIdx.x;
    if (e < E) {
        int p = atomicAdd(&cur[col[e]], 1);
        esrc[p] = row[e];
        eidx[p] = e;
    }
}

// ---------------- weight conversion ----------------
__global__ void conv_w(const float* __restrict__ src, __half* __restrict__ dst, int count) {
    int i = blockIdx.x * blockDim.x + threadIdx.x;
    if (i < count) dst[i] = __float2half_rn(src[i]);
}
__global__ void repack_wab_h(const float* __restrict__ l1W, __half* __restrict__ wabh) {
    int i = blockIdx.x * blockDim.x + threadIdx.x;
    if (i < 64 * 128) {
        int k = i >> 7, nn = i & 127;
        float v = (nn < 64) ? l1W[k * 64 + nn] : l1W[(64 + k) * 64 + (nn - 64)];
        wabh[i] = __float2half_rn(v);
    }
}

__device__ __forceinline__ __half2 as_h2(unsigned u) { return *reinterpret_cast<__half2*>(&u); }

__device__ __forceinline__ void acc_f32_u4(float4& a, float4& b, uint4 u) {
    float2 f0 = __half22float2(as_h2(u.x));
    float2 f1 = __half22float2(as_h2(u.y));
    float2 f2 = __half22float2(as_h2(u.z));
    float2 f3 = __half22float2(as_h2(u.w));
    a.x += f0.x; a.y += f0.y; a.z += f1.x; a.w += f1.y;
    b.x += f2.x; b.y += f2.y; b.z += f3.x; b.w += f3.y;
}
__device__ __forceinline__ void acc_pair_u4(float4& a, float4& b, uint4 u0, uint4 u1) {
    __half2 p0 = __hadd2(as_h2(u0.x), as_h2(u1.x));
    __half2 p1 = __hadd2(as_h2(u0.y), as_h2(u1.y));
    __half2 p2 = __hadd2(as_h2(u0.z), as_h2(u1.z));
    __half2 p3 = __hadd2(as_h2(u0.w), as_h2(u1.w));
    float2 f0 = __half22float2(p0);
    float2 f1 = __half22float2(p1);
    float2 f2 = __half22float2(p2);
    float2 f3 = __half22float2(p3);
    a.x += f0.x; a.y += f0.y; a.z += f1.x; a.w += f1.y;
    b.x += f2.x; b.y += f2.y; b.z += f3.x; b.w += f3.y;
}

// ---------------- MMA core (64-row tile from smem Xs) ----------------
template <int K, int N, bool SCALE>
__device__ __forceinline__ void mma_tile(const __half* Xs, const __half* Ws,
                                         const float* __restrict__ dinv,
                                         __half2* __restrict__ Y, int row0, int nrows,
                                         int warp, int lane) {
    constexpr int XP = K + 8;
    constexpr int WP = N + 8;
    float acc[N / 8][4];
#pragma unroll
    for (int nt = 0; nt < N / 8; nt++)
#pragma unroll
        for (int q = 0; q < 4; q++) acc[nt][q] = 0.f;

    int arow = warp * 16 + (lane & 15);
    int acol = (lane >> 4) * 8;
    int brow_l = lane & 15;

#pragma unroll
    for (int kt = 0; kt < K / 16; kt++) {
        unsigned a0, a1, a2, a3;
        unsigned aaddr = (unsigned)__cvta_generic_to_shared(&Xs[arow * XP + kt * 16 + acol]);
        asm volatile("ldmatrix.sync.aligned.m8n8.x4.shared.b16 {%0,%1,%2,%3}, [%4];"
                     : "=r"(a0), "=r"(a1), "=r"(a2), "=r"(a3) : "r"(aaddr));
#pragma unroll
        for (int nt = 0; nt < N / 8; nt++) {
            unsigned b0, b1;
            unsigned baddr = (unsigned)__cvta_generic_to_shared(
                &Ws[(kt * 16 + brow_l) * WP + nt * 8]);
            asm volatile("ldmatrix.sync.aligned.m8n8.x2.trans.shared.b16 {%0,%1}, [%2];"
                         : "=r"(b0), "=r"(b1) : "r"(baddr));
            asm volatile(
                "mma.sync.aligned.m16n8k16.row.col.f32.f16.f16.f32 "
                "{%0,%1,%2,%3}, {%4,%5,%6,%7}, {%8,%9}, {%0,%1,%2,%3};"
                : "+f"(acc[nt][0]), "+f"(acc[nt][1]), "+f"(acc[nt][2]), "+f"(acc[nt][3])
                : "r"(a0), "r"(a1), "r"(a2), "r"(a3), "r"(b0), "r"(b1));
        }
    }

    int rr = warp * 16 + (lane >> 2);
    int cq = lane & 3;
#pragma unroll
    for (int hh = 0; hh < 2; hh++) {
        int gr = row0 + rr + hh * 8;
        if (gr < nrows) {
            float s = SCALE ? dinv[gr] : 1.0f;
#pragma unroll
            for (int nt = 0; nt < N / 8; nt++) {
                __half2 p = __floats2half2_rn(acc[nt][hh * 2 + 0] * s,
                                              acc[nt][hh * 2 + 1] * s);
                Y[(size_t)gr * (N / 2) + nt * 4 + cq] = p;
            }
        }
    }
}

// ---------------- gemm1: X fp32 -> Xs fp16, then MMA ----------------
template <int K, int N>
__global__ void gemm_mma_f32(const float* __restrict__ X, const __half* __restrict__ Wh,
                             const float* __restrict__ dinv, __half2* __restrict__ Y, int nrows) {
    constexpr int XP = K + 8;
    constexpr int WP = N + 8;
    __shared__ __half Xs[64 * XP];
    __shared__ __half Ws[K * WP];
    int tid = threadIdx.x;
    int row0 = blockIdx.x * 64;
    for (int j = tid; j < 64 * (K / 4); j += 128) {
        int r = j / (K / 4), kq = j % (K / 4);
        int gr = row0 + r;
        float4 v = (gr < nrows)
            ? *reinterpret_cast<const float4*>(&X[(size_t)gr * K + kq * 4])
            : make_float4(0.f, 0.f, 0.f, 0.f);
        __half2 h0 = __floats2half2_rn(v.x, v.y);
        __half2 h1 = __floats2half2_rn(v.z, v.w);
        uint2 u;
        u.x = *reinterpret_cast<unsigned*>(&h0);
        u.y = *reinterpret_cast<unsigned*>(&h1);
        *reinterpret_cast<uint2*>(&Xs[r * XP + kq * 4]) = u;
    }
    for (int j = tid; j < K * (N / 8); j += 128) {
        int k = j / (N / 8), nq = j % (N / 8);
        *reinterpret_cast<uint4*>(&Ws[k * WP + nq * 8]) =
            *reinterpret_cast<const uint4*>(&Wh[(size_t)k * N + nq * 8]);
    }
    __syncthreads();
    mma_tile<K, N, true>(Xs, Ws, dinv, Y, row0, nrows, tid >> 5, tid & 31);
}

// ---------------- fused gather + gemm ----------------
// Gathers 64 nodes (relu(dinv*(sum+self)+bias), fp16) directly into Xs, then MMA.
// src pre-scaled by dinv[src]. Output optionally pre-scaled (for next layer).
template <int N, bool SCALE>
__global__ void gather_gemm(const int* __restrict__ off, const int* __restrict__ esrc,
                            const __half2* __restrict__ src, const float* __restrict__ dinv,
                            const float* __restrict__ bias, const __half* __restrict__ Wh,
                            __half2* __restrict__ Y, int n) {
    constexpr int K = 64;
    constexpr int XP = K + 8;
    constexpr int WP = N + 8;
    __shared__ __half Xs[64 * XP];
    __shared__ __half Ws[K * WP];
    int tid = threadIdx.x;
    int row0 = blockIdx.x * 64;

    // stage W
    for (int j = tid; j < K * (N / 8); j += 128) {
        int k = j / (N / 8), nq = j % (N / 8);
        *reinterpret_cast<uint4*>(&Ws[k * WP + nq * 8]) =
            *reinterpret_cast<const uint4*>(&Wh[(size_t)k * N + nq * 8]);
    }

    // gather phase: 16 nodes per pass (8 lanes x 16), 4 passes
    const uint4* hp = reinterpret_cast<const uint4*>(src);
    int l = tid & 7;
    int jb = l * 8;
    float4 bia = *reinterpret_cast<const float4*>(&bias[jb]);
    float4 bib = *reinterpret_cast<const float4*>(&bias[jb + 4]);
#pragma unroll
    for (int pass = 0; pass < 4; pass++) {
        int cl = pass * 16 + (tid >> 3);
        int c = row0 + cl;
        uint4 o = make_uint4(0, 0, 0, 0);
        if (c < n) {
            float dc = dinv[c];
            float4 a = make_float4(0.f, 0.f, 0.f, 0.f);
            float4 b = make_float4(0.f, 0.f, 0.f, 0.f);
            acc_f32_u4(a, b, hp[(size_t)c * 8 + l]);  // self (pre-scaled)
            int s = off[c], e2 = off[c + 1];
            int j = s;
            for (; j + 3 < e2; j += 4) {
                int r0 = esrc[j], r1 = esrc[j + 1], r2 = esrc[j + 2], r3 = esrc[j + 3];
                uint4 u0 = hp[(size_t)r0 * 8 + l];
                uint4 u1 = hp[(size_t)r1 * 8 + l];
                uint4 u2 = hp[(size_t)r2 * 8 + l];
                uint4 u3 = hp[(size_t)r3 * 8 + l];
                acc_pair_u4(a, b, u0, u1);
                acc_pair_u4(a, b, u2, u3);
            }
            for (; j + 1 < e2; j += 2) {
                uint4 u0 = hp[(size_t)esrc[j] * 8 + l];
                uint4 u1 = hp[(size_t)esrc[j + 1] * 8 + l];
                acc_pair_u4(a, b, u0, u1);
            }
            if (j < e2) acc_f32_u4(a, b, hp[(size_t)esrc[j] * 8 + l]);
            __half2 p0 = __floats2half2_rn(fmaxf(a.x * dc + bia.x, 0.f), fmaxf(a.y * dc + bia.y, 0.f));
            __half2 p1 = __floats2half2_rn(fmaxf(a.z * dc + bia.z, 0.f), fmaxf(a.w * dc + bia.w, 0.f));
            __half2 p2 = __floats2half2_rn(fmaxf(b.x * dc + bib.x, 0.f), fmaxf(b.y * dc + bib.y, 0.f));
            __half2 p3 = __floats2half2_rn(fmaxf(b.z * dc + bib.z, 0.f), fmaxf(b.w * dc + bib.w, 0.f));
            o.x = *reinterpret_cast<unsigned*>(&p0);
            o.y = *reinterpret_cast<unsigned*>(&p1);
            o.z = *reinterpret_cast<unsigned*>(&p2);
            o.w = *reinterpret_cast<unsigned*>(&p3);
        }
        *reinterpret_cast<uint4*>(&Xs[cl * XP + l * 8]) = o;
    }
    __syncthreads();
    mma_tile<K, N, SCALE>(Xs, Ws, dinv, Y, row0, n, tid >> 5, tid & 31);
}

// ---------------- edge MLP, CSC-ordered ----------------
__global__ void edge_mlp_csc(const int* __restrict__ off, const int* __restrict__ esrc,
                             const int* __restrict__ eidx, const __half2* __restrict__ ab,
                             const float* __restrict__ l1b, const float* __restrict__ l2w,
                             const float* __restrict__ l2b, float* __restrict__ out, int n) {
    __shared__ __half2 s1bh[32];
    __shared__ float swd[64];
    __shared__ float sdb;
    int tid = threadIdx.x;
    if (tid < 32)       s1bh[tid] = __floats2half2_rn(l1b[tid * 2], l1b[tid * 2 + 1]);
    else if (tid < 96)  swd[tid - 32] = l2w[(tid - 32) * 2] - l2w[(tid - 32) * 2 + 1];
    else if (tid == 96) sdb = l2b[0] - l2b[1];
    __syncthreads();
    int gid = blockIdx.x * 256 + tid;
    int c = gid >> 3;
    if (c >= n) return;
    int l = gid & 7;
    const uint4* ap = reinterpret_cast<const uint4*>(ab);
    uint4 ub = ap[(size_t)c * 16 + 8 + l];
    __half2 hb0 = __hadd2(as_h2(ub.x), s1bh[l * 4 + 0]);
    __half2 hb1 = __hadd2(as_h2(ub.y), s1bh[l * 4 + 1]);
    __half2 hb2 = __hadd2(as_h2(ub.z), s1bh[l * 4 + 2]);
    __half2 hb3 = __hadd2(as_h2(ub.w), s1bh[l * 4 + 3]);
    const __half2 hz = __float2half2_rn(0.f);
    int j = l * 8;
    float w0 = swd[j + 0], w1 = swd[j + 1], w2 = swd[j + 2], w3 = swd[j + 3];
    float w4 = swd[j + 4], w5 = swd[j + 5], w6 = swd[j + 6], w7 = swd[j + 7];
    int s = off[c], e2 = off[c + 1];
    for (int p = s; p < e2; p++) {
        int r = esrc[p];
        uint4 ua = ap[(size_t)r * 16 + l];
        __half2 z0 = __hmax2(__hadd2(as_h2(ua.x), hb0), hz);
        __half2 z1 = __hmax2(__hadd2(as_h2(ua.y), hb1), hz);
        __half2 z2 = __hmax2(__hadd2(as_h2(ua.z), hb2), hz);
        __half2 z3 = __hmax2(__hadd2(as_h2(ua.w), hb3), hz);
        float2 f0 = __half22float2(z0);
        float2 f1 = __half22float2(z1);
        float2 f2 = __half22float2(z2);
        float2 f3 = __half22float2(z3);
        float d = f0.x * w0 + f0.y * w1 + f1.x * w2 + f1.y * w3
                + f2.x * w4 + f2.y * w5 + f3.x * w6 + f3.y * w7;
#pragma unroll
        for (int o = 4; o > 0; o >>= 1)
            d += __shfl_down_sync(0xFFFFFFFFu, d, o, 8);
        if (l == 0) {
            d += sdb;
            float ad = fabsf(d);
            float lp = log1pf(__expf(-ad));
            float o0 = (d > 0.f) ? -lp : (d - lp);
            float o1 = o0 - d;
            int e = eidx[p];
            *reinterpret_cast<float2*>(&out[2 * (size_t)e]) = make_float2(o0, o1);
        }
    }
}

extern "C" void kernel_launch(void* const* d_in, const int* in_sizes, int n_in,
                              void* d_out, int out_size) {
    const float* x   = (const float*)d_in[0];
    const int*   ei  = (const int*)d_in[1];
    const float* W1  = (const float*)d_in[2];
    const float* b1  = (const float*)d_in[3];
    const float* W2  = (const float*)d_in[4];
    const float* b2  = (const float*)d_in[5];
    const float* l1W = (const float*)d_in[6];
    const float* l1b = (const float*)d_in[7];
    const float* l2W = (const float*)d_in[8];
    const float* l2b = (const float*)d_in[9];
    float* out = (float*)d_out;

    int n = in_sizes[0] / FIN;
    int E = in_sizes[1] / 2;
    const int* row = ei;
    const int* col = ei + E;

    int *cnt, *off, *cur, *esrc, *eidx, *bsum;
    float *dinv;
    __half2 *hl2, *hl2b, *ab2;
    __half *w1h, *w2h, *wabh;
    cudaGetSymbolAddress((void**)&cnt,  g_cnt);
    cudaGetSymbolAddress((void**)&off,  g_off);
    cudaGetSymbolAddress((void**)&cur,  g_cur);
    cudaGetSymbolAddress((void**)&esrc, g_esrc);
    cudaGetSymbolAddress((void**)&eidx, g_eidx);
    cudaGetSymbolAddress((void**)&bsum, g_bsum);
    cudaGetSymbolAddress((void**)&dinv, g_dinv);
    cudaGetSymbolAddress((void**)&hl2,  g_hl2);
    cudaGetSymbolAddress((void**)&hl2b, g_hl2b);
    cudaGetSymbolAddress((void**)&ab2,  g_ab2);
    cudaGetSymbolAddress((void**)&w1h,  g_w1h);
    cudaGetSymbolAddress((void**)&w2h,  g_w2h);
    cudaGetSymbolAddress((void**)&wabh, g_wabh);

    const int T = 256;
    int NB = (n + 255) / 256;

    // fork: CSR build + weight conversions on side stream
    cudaMemsetAsync(cnt, 0, (size_t)n * sizeof(int), 0);
    cudaEventRecord(g_evFork, 0);
    cudaStreamWaitEvent(g_s2, g_evFork, 0);
    count_in<<<(E + T - 1) / T, T, 0, g_s2>>>(col, cnt, E);
    scan1<<<NB, T, 0, g_s2>>>(cnt, off, bsum, dinv, n);
    cudaEventRecord(g_evDinv, g_s2);
    scan2<<<1, 512, 0, g_s2>>>(bsum, NB);
    scan3<<<NB, T, 0, g_s2>>>(off, bsum, cur, n, E);
    fill_csr<<<(E + T - 1) / T, T, 0, g_s2>>>(row, col, cur, esrc, eidx, E);
    conv_w<<<(HIDD * HIDD + T - 1) / T, T, 0, g_s2>>>(W2, w2h, HIDD * HIDD);
    repack_wab_h<<<(64 * 128 + T - 1) / T, T, 0, g_s2>>>(l1W, wabh);
    cudaEventRecord(g_evJoin, g_s2);

    // main: W1 conversion overlaps count_in; gemm1 waits only for dinv
    conv_w<<<(FIN * HIDD + T - 1) / T, T>>>(W1, w1h, FIN * HIDD);
    cudaStreamWaitEvent(0, g_evDinv, 0);
    gemm_mma_f32<128, 64><<<(n + 63) / 64, 128>>>(x, w1h, dinv, hl2, n);
    cudaStreamWaitEvent(0, g_evJoin, 0);

    // fused: gather(layer1) + gemm2 -> hl2b (pre-scaled)
    gather_gemm<64, true><<<(n + 63) / 64, 128>>>(off, esrc, hl2, dinv, b1, w2h, hl2b, n);
    // fused: gather(layer2) + gemm3 -> ab2
    gather_gemm<128, false><<<(n + 63) / 64, 128>>>(off, esrc, hl2b, dinv, b2, wabh, ab2, n);

    edge_mlp_csc<<<(n * 8 + T - 1) / T, T>>>(off, esrc, eidx, ab2, l1b, l2W, l2b, out, n);
}

// round 13
// speedup vs baseline: 1.4225x; 1.4225x over previous
#include <cuda_runtime.h>
#include <cuda_fp16.h>

#define NMAX 100000
#define EMAX 1600000
#define HIDD 64
#define FIN  128

__device__ int     g_cnt[NMAX];
__device__ int     g_off[NMAX + 1];
__device__ int     g_cur[NMAX];
__device__ int     g_esrc[EMAX];
__device__ int     g_eidx[EMAX];
__device__ int     g_bsum[512];
__device__ float   g_dinv[NMAX];
__device__ __half2 g_hl2[NMAX * HIDD / 2];   // fp16, PRE-SCALED by dinv[src]
__device__ __half2 g_h2 [NMAX * HIDD / 2];   // fp16 aggregated features
__device__ __half2 g_ab2[NMAX * HIDD];       // fp16 [A|B] table
__device__ __half  g_w1h[FIN * HIDD];
__device__ __half  g_w2h[HIDD * HIDD];
__device__ __half  g_wabh[HIDD * 2 * HIDD];

static cudaStream_t g_s2;
static cudaEvent_t g_evFork, g_evDinv, g_evJoin;
namespace { struct StreamInit {
    StreamInit() {
        cudaStreamCreateWithFlags(&g_s2, cudaStreamNonBlocking);
        cudaEventCreateWithFlags(&g_evFork, cudaEventDisableTiming);
        cudaEventCreateWithFlags(&g_evDinv, cudaEventDisableTiming);
        cudaEventCreateWithFlags(&g_evJoin, cudaEventDisableTiming);
    }
} g_streamInit; }

// ---------------- CSC build ----------------
__global__ void count_in(const int* __restrict__ col, int* __restrict__ cnt, int E) {
    int e = blockIdx.x * blockDim.x + threadIdx.x;
    if (e < E) atomicAdd(&cnt[col[e]], 1);
}
__global__ void scan1(const int* __restrict__ cnt, int* __restrict__ off,
                      int* __restrict__ bsum, float* __restrict__ dinv, int n) {
    __shared__ int s[256];
    int tid = threadIdx.x;
    int i = blockIdx.x * 256 + tid;
    int v = (i < n) ? cnt[i] : 0;
    if (i < n) dinv[i] = rsqrtf((float)v + 1.0f);
    s[tid] = v;
    __syncthreads();
#pragma unroll
    for (int d = 1; d < 256; d <<= 1) {
        int t = (tid >= d) ? s[tid - d] : 0;
        __syncthreads();
        s[tid] += t;
        __syncthreads();
    }
    if (i < n) off[i] = s[tid] - v;
    if (tid == 255) bsum[blockIdx.x] = s[255];
}
__global__ void scan2(int* __restrict__ bsum, int nb) {
    __shared__ int s[512];
    int tid = threadIdx.x;
    int v = (tid < nb) ? bsum[tid] : 0;
    s[tid] = v;
    __syncthreads();
#pragma unroll
    for (int d = 1; d < 512; d <<= 1) {
        int t = (tid >= d) ? s[tid - d] : 0;
        __syncthreads();
        s[tid] += t;
        __syncthreads();
    }
    if (tid < nb) bsum[tid] = s[tid] - v;
}
__global__ void scan3(int* __restrict__ off, const int* __restrict__ bsum,
                      int* __restrict__ cur, int n, int E) {
    int i = blockIdx.x * 256 + threadIdx.x;
    if (i < n) {
        int o = off[i] + bsum[blockIdx.x];
        off[i] = o;
        cur[i] = o;
    }
    if (i == 0) off[n] = E;
}
__global__ void fill_csr(const int* __restrict__ row, const int* __restrict__ col,
                         int* __restrict__ cur, int* __restrict__ esrc,
                         int* __restrict__ eidx, int E) {
    int e = blockIdx.x * blockDim.x + threadIdx.x;
    if (e < E) {
        int p = atomicAdd(&cur[col[e]], 1);
        esrc[p] = row[e];
        eidx[p] = e;
    }
}

// ---------------- weight conversion ----------------
__global__ void conv_w(const float* __restrict__ src, __half* __restrict__ dst, int count) {
    int i = blockIdx.x * blockDim.x + threadIdx.x;
    if (i < count) dst[i] = __float2half_rn(src[i]);
}
__global__ void repack_wab_h(const float* __restrict__ l1W, __half* __restrict__ wabh) {
    int i = blockIdx.x * blockDim.x + threadIdx.x;
    if (i < 64 * 128) {
        int k = i >> 7, nn = i & 127;
        float v = (nn < 64) ? l1W[k * 64 + nn] : l1W[(64 + k) * 64 + (nn - 64)];
        wabh[i] = __float2half_rn(v);
    }
}

// ---------------- HMMA GEMM ----------------
template <int K, int N, bool SCALE, bool HALF_IN>
__global__ void gemm_mma(const void* __restrict__ Xv, const __half* __restrict__ Wh,
                         const float* __restrict__ dinv, __half2* __restrict__ Y, int nrows) {
    constexpr int XP = K + 8;
    constexpr int WP = N + 8;
    __shared__ __half Xs[64 * XP];
    __shared__ __half Ws[K * WP];
    int tid = threadIdx.x;
    int warp = tid >> 5, lane = tid & 31;
    int row0 = blockIdx.x * 64;

    if (HALF_IN) {
        const __half* X = (const __half*)Xv;
        for (int j = tid; j < 64 * (K / 8); j += 128) {
            int r = j / (K / 8), kq = j % (K / 8);
            int gr = row0 + r;
            uint4 u = make_uint4(0, 0, 0, 0);
            if (gr < nrows) u = *reinterpret_cast<const uint4*>(&X[(size_t)gr * K + kq * 8]);
            *reinterpret_cast<uint4*>(&Xs[r * XP + kq * 8]) = u;
        }
    } else {
        const float* X = (const float*)Xv;
        for (int j = tid; j < 64 * (K / 4); j += 128) {
            int r = j / (K / 4), kq = j % (K / 4);
            int gr = row0 + r;
            float4 v = (gr < nrows)
                ? *reinterpret_cast<const float4*>(&X[(size_t)gr * K + kq * 4])
                : make_float4(0.f, 0.f, 0.f, 0.f);
            __half2 h0 = __floats2half2_rn(v.x, v.y);
            __half2 h1 = __floats2half2_rn(v.z, v.w);
            uint2 u;
            u.x = *reinterpret_cast<unsigned*>(&h0);
            u.y = *reinterpret_cast<unsigned*>(&h1);
            *reinterpret_cast<uint2*>(&Xs[r * XP + kq * 4]) = u;
        }
    }
    for (int j = tid; j < K * (N / 8); j += 128) {
        int k = j / (N / 8), nq = j % (N / 8);
        *reinterpret_cast<uint4*>(&Ws[k * WP + nq * 8]) =
            *reinterpret_cast<const uint4*>(&Wh[(size_t)k * N + nq * 8]);
    }
    __syncthreads();

    float acc[N / 8][4];
#pragma unroll
    for (int nt = 0; nt < N / 8; nt++)
#pragma unroll
        for (int q = 0; q < 4; q++) acc[nt][q] = 0.f;

    int arow = warp * 16 + (lane & 15);
    int acol = (lane >> 4) * 8;
    int brow_l = lane & 15;

#pragma unroll
    for (int kt = 0; kt < K / 16; kt++) {
        unsigned a0, a1, a2, a3;
        unsigned aaddr = (unsigned)__cvta_generic_to_shared(&Xs[arow * XP + kt * 16 + acol]);
        asm volatile("ldmatrix.sync.aligned.m8n8.x4.shared.b16 {%0,%1,%2,%3}, [%4];"
                     : "=r"(a0), "=r"(a1), "=r"(a2), "=r"(a3) : "r"(aaddr));
#pragma unroll
        for (int nt = 0; nt < N / 8; nt++) {
            unsigned b0, b1;
            unsigned baddr = (unsigned)__cvta_generic_to_shared(
                &Ws[(kt * 16 + brow_l) * WP + nt * 8]);
            asm volatile("ldmatrix.sync.aligned.m8n8.x2.trans.shared.b16 {%0,%1}, [%2];"
                         : "=r"(b0), "=r"(b1) : "r"(baddr));
            asm volatile(
                "mma.sync.aligned.m16n8k16.row.col.f32.f16.f16.f32 "
                "{%0,%1,%2,%3}, {%4,%5,%6,%7}, {%8,%9}, {%0,%1,%2,%3};"
                : "+f"(acc[nt][0]), "+f"(acc[nt][1]), "+f"(acc[nt][2]), "+f"(acc[nt][3])
                : "r"(a0), "r"(a1), "r"(a2), "r"(a3), "r"(b0), "r"(b1));
        }
    }

    int rr = warp * 16 + (lane >> 2);
    int cq = lane & 3;
#pragma unroll
    for (int hh = 0; hh < 2; hh++) {
        int gr = row0 + rr + hh * 8;
        if (gr < nrows) {
            float s = SCALE ? dinv[gr] : 1.0f;
#pragma unroll
            for (int nt = 0; nt < N / 8; nt++) {
                __half2 p = __floats2half2_rn(acc[nt][hh * 2 + 0] * s,
                                              acc[nt][hh * 2 + 1] * s);
                Y[(size_t)gr * (N / 2) + nt * 4 + cq] = p;
            }
        }
    }
}

__device__ __forceinline__ __half2 as_h2(unsigned u) { return *reinterpret_cast<__half2*>(&u); }

__device__ __forceinline__ void acc_f32_u4(float4& a, float4& b, uint4 u) {
    float2 f0 = __half22float2(as_h2(u.x));
    float2 f1 = __half22float2(as_h2(u.y));
    float2 f2 = __half22float2(as_h2(u.z));
    float2 f3 = __half22float2(as_h2(u.w));
    a.x += f0.x; a.y += f0.y; a.z += f1.x; a.w += f1.y;
    b.x += f2.x; b.y += f2.y; b.z += f3.x; b.w += f3.y;
}
__device__ __forceinline__ void acc_pair_u4(float4& a, float4& b, uint4 u0, uint4 u1) {
    __half2 p0 = __hadd2(as_h2(u0.x), as_h2(u1.x));
    __half2 p1 = __hadd2(as_h2(u0.y), as_h2(u1.y));
    __half2 p2 = __hadd2(as_h2(u0.z), as_h2(u1.z));
    __half2 p3 = __hadd2(as_h2(u0.w), as_h2(u1.w));
    float2 f0 = __half22float2(p0);
    float2 f1 = __half22float2(p1);
    float2 f2 = __half22float2(p2);
    float2 f3 = __half22float2(p3);
    a.x += f0.x; a.y += f0.y; a.z += f1.x; a.w += f1.y;
    b.x += f2.x; b.y += f2.y; b.z += f3.x; b.w += f3.y;
}

// ---------------- aggregation: sources pre-scaled; 8 lanes/node; MLP=8 ----------------
__global__ void gather_agg(const int* __restrict__ off, const int* __restrict__ esrc,
                           const __half2* __restrict__ hls, const float* __restrict__ dinv,
                           const float* __restrict__ bias, __half2* __restrict__ h, int n) {
    __shared__ float sb[64];
    if (threadIdx.x < 64) sb[threadIdx.x] = bias[threadIdx.x];
    __syncthreads();
    int gid = blockIdx.x * 256 + threadIdx.x;
    int c = gid >> 3;
    if (c >= n) return;
    int l = gid & 7;
    const uint4* hp = reinterpret_cast<const uint4*>(hls);
    float dc = dinv[c];
    float4 a = make_float4(0.f, 0.f, 0.f, 0.f);
    float4 b = make_float4(0.f, 0.f, 0.f, 0.f);
    acc_f32_u4(a, b, hp[(size_t)c * 8 + l]);  // self (pre-scaled)
    int s = off[c], e2 = off[c + 1];
    int j = s;
    for (; j + 7 < e2; j += 8) {
        int r0 = esrc[j],     r1 = esrc[j + 1], r2 = esrc[j + 2], r3 = esrc[j + 3];
        int r4 = esrc[j + 4], r5 = esrc[j + 5], r6 = esrc[j + 6], r7 = esrc[j + 7];
        uint4 u0 = hp[(size_t)r0 * 8 + l];
        uint4 u1 = hp[(size_t)r1 * 8 + l];
        uint4 u2 = hp[(size_t)r2 * 8 + l];
        uint4 u3 = hp[(size_t)r3 * 8 + l];
        uint4 u4 = hp[(size_t)r4 * 8 + l];
        uint4 u5 = hp[(size_t)r5 * 8 + l];
        uint4 u6 = hp[(size_t)r6 * 8 + l];
        uint4 u7 = hp[(size_t)r7 * 8 + l];
        acc_pair_u4(a, b, u0, u1);
        acc_pair_u4(a, b, u2, u3);
        acc_pair_u4(a, b, u4, u5);
        acc_pair_u4(a, b, u6, u7);
    }
    for (; j + 1 < e2; j += 2) {
        uint4 u0 = hp[(size_t)esrc[j] * 8 + l];
        uint4 u1 = hp[(size_t)esrc[j + 1] * 8 + l];
        acc_pair_u4(a, b, u0, u1);
    }
    if (j < e2) acc_f32_u4(a, b, hp[(size_t)esrc[j] * 8 + l]);
    int jb = l * 8;
    __half2 p0 = __floats2half2_rn(fmaxf(a.x * dc + sb[jb + 0], 0.f), fmaxf(a.y * dc + sb[jb + 1], 0.f));
    __half2 p1 = __floats2half2_rn(fmaxf(a.z * dc + sb[jb + 2], 0.f), fmaxf(a.w * dc + sb[jb + 3], 0.f));
    __half2 p2 = __floats2half2_rn(fmaxf(b.x * dc + sb[jb + 4], 0.f), fmaxf(b.y * dc + sb[jb + 5], 0.f));
    __half2 p3 = __floats2half2_rn(fmaxf(b.z * dc + sb[jb + 6], 0.f), fmaxf(b.w * dc + sb[jb + 7], 0.f));
    uint4 o;
    o.x = *reinterpret_cast<unsigned*>(&p0);
    o.y = *reinterpret_cast<unsigned*>(&p1);
    o.z = *reinterpret_cast<unsigned*>(&p2);
    o.w = *reinterpret_cast<unsigned*>(&p3);
    reinterpret_cast<uint4*>(h)[(size_t)c * 8 + l] = o;
}

// ---------------- edge MLP, CSC-ordered: 2 edges in flight ----------------
__global__ void edge_mlp_csc(const int* __restrict__ off, const int* __restrict__ esrc,
                             const int* __restrict__ eidx, const __half2* __restrict__ ab,
                             const float* __restrict__ l1b, const float* __restrict__ l2w,
                             const float* __restrict__ l2b, float* __restrict__ out, int n) {
    __shared__ __half2 s1bh[32];
    __shared__ float swd[64];
    __shared__ float sdb;
    int tid = threadIdx.x;
    if (tid < 32)       s1bh[tid] = __floats2half2_rn(l1b[tid * 2], l1b[tid * 2 + 1]);
    else if (tid < 96)  swd[tid - 32] = l2w[(tid - 32) * 2] - l2w[(tid - 32) * 2 + 1];
    else if (tid == 96) sdb = l2b[0] - l2b[1];
    __syncthreads();
    int gid = blockIdx.x * 256 + tid;
    int c = gid >> 3;
    if (c >= n) return;
    int l = gid & 7;
    const uint4* ap = reinterpret_cast<const uint4*>(ab);
    uint4 ub = ap[(size_t)c * 16 + 8 + l];
    __half2 hb0 = __hadd2(as_h2(ub.x), s1bh[l * 4 + 0]);
    __half2 hb1 = __hadd2(as_h2(ub.y), s1bh[l * 4 + 1]);
    __half2 hb2 = __hadd2(as_h2(ub.z), s1bh[l * 4 + 2]);
    __half2 hb3 = __hadd2(as_h2(ub.w), s1bh[l * 4 + 3]);
    const __half2 hz = __float2half2_rn(0.f);
    int j = l * 8;
    float w0 = swd[j + 0], w1 = swd[j + 1], w2 = swd[j + 2], w3 = swd[j + 3];
    float w4 = swd[j + 4], w5 = swd[j + 5], w6 = swd[j + 6], w7 = swd[j + 7];
    int s = off[c], e2 = off[c + 1];
    int p = s;
    for (; p + 1 < e2; p += 2) {
        int r0 = esrc[p], r1 = esrc[p + 1];
        uint4 ua0 = ap[(size_t)r0 * 16 + l];
        uint4 ua1 = ap[(size_t)r1 * 16 + l];
        // edge 0
        __half2 z0 = __hmax2(__hadd2(as_h2(ua0.x), hb0), hz);
        __half2 z1 = __hmax2(__hadd2(as_h2(ua0.y), hb1), hz);
        __half2 z2 = __hmax2(__hadd2(as_h2(ua0.z), hb2), hz);
        __half2 z3 = __hmax2(__hadd2(as_h2(ua0.w), hb3), hz);
        float2 f0 = __half22float2(z0), f1 = __half22float2(z1);
        float2 f2 = __half22float2(z2), f3 = __half22float2(z3);
        float d0 = f0.x * w0 + f0.y * w1 + f1.x * w2 + f1.y * w3
                 + f2.x * w4 + f2.y * w5 + f3.x * w6 + f3.y * w7;
        // edge 1
        __half2 y0 = __hmax2(__hadd2(as_h2(ua1.x), hb0), hz);
        __half2 y1 = __hmax2(__hadd2(as_h2(ua1.y), hb1), hz);
        __half2 y2 = __hmax2(__hadd2(as_h2(ua1.z), hb2), hz);
        __half2 y3 = __hmax2(__hadd2(as_h2(ua1.w), hb3), hz);
        float2 g0 = __half22float2(y0), g1 = __half22float2(y1);
        float2 g2 = __half22float2(y2), g3 = __half22float2(y3);
        float d1 = g0.x * w0 + g0.y * w1 + g1.x * w2 + g1.y * w3
                 + g2.x * w4 + g2.y * w5 + g3.x * w6 + g3.y * w7;
#pragma unroll
        for (int o = 4; o > 0; o >>= 1) {
            d0 += __shfl_down_sync(0xFFFFFFFFu, d0, o, 8);
            d1 += __shfl_down_sync(0xFFFFFFFFu, d1, o, 8);
        }
        if (l == 0) {
            float da = d0 + sdb;
            float lpa = log1pf(__expf(-fabsf(da)));
            float oa0 = (da > 0.f) ? -lpa : (da - lpa);
            *reinterpret_cast<float2*>(&out[2 * (size_t)eidx[p]]) = make_float2(oa0, oa0 - da);
            float db = d1 + sdb;
            float lpb = log1pf(__expf(-fabsf(db)));
            float ob0 = (db > 0.f) ? -lpb : (db - lpb);
            *reinterpret_cast<float2*>(&out[2 * (size_t)eidx[p + 1]]) = make_float2(ob0, ob0 - db);
        }
    }
    if (p < e2) {
        int r = esrc[p];
        uint4 ua = ap[(size_t)r * 16 + l];
        __half2 z0 = __hmax2(__hadd2(as_h2(ua.x), hb0), hz);
        __half2 z1 = __hmax2(__hadd2(as_h2(ua.y), hb1), hz);
        __half2 z2 = __hmax2(__hadd2(as_h2(ua.z), hb2), hz);
        __half2 z3 = __hmax2(__hadd2(as_h2(ua.w), hb3), hz);
        float2 f0 = __half22float2(z0), f1 = __half22float2(z1);
        float2 f2 = __half22float2(z2), f3 = __half22float2(z3);
        float d = f0.x * w0 + f0.y * w1 + f1.x * w2 + f1.y * w3
                + f2.x * w4 + f2.y * w5 + f3.x * w6 + f3.y * w7;
#pragma unroll
        for (int o = 4; o > 0; o >>= 1)
            d += __shfl_down_sync(0xFFFFFFFFu, d, o, 8);
        if (l == 0) {
            d += sdb;
            float lp = log1pf(__expf(-fabsf(d)));
            float o0 = (d > 0.f) ? -lp : (d - lp);
            *reinterpret_cast<float2*>(&out[2 * (size_t)eidx[p]]) = make_float2(o0, o0 - d);
        }
    }
}

extern "C" void kernel_launch(void* const* d_in, const int* in_sizes, int n_in,
                              void* d_out, int out_size) {
    const float* x   = (const float*)d_in[0];
    const int*   ei  = (const int*)d_in[1];
    const float* W1  = (const float*)d_in[2];
    const float* b1  = (const float*)d_in[3];
    const float* W2  = (const float*)d_in[4];
    const float* b2  = (const float*)d_in[5];
    const float* l1W = (const float*)d_in[6];
    const float* l1b = (const float*)d_in[7];
    const float* l2W = (const float*)d_in[8];
    const float* l2b = (const float*)d_in[9];
    float* out = (float*)d_out;

    int n = in_sizes[0] / FIN;
    int E = in_sizes[1] / 2;
    const int* row = ei;
    const int* col = ei + E;

    int *cnt, *off, *cur, *esrc, *eidx, *bsum;
    float *dinv;
    __half2 *hl2, *h2, *ab2;
    __half *w1h, *w2h, *wabh;
    cudaGetSymbolAddress((void**)&cnt,  g_cnt);
    cudaGetSymbolAddress((void**)&off,  g_off);
    cudaGetSymbolAddress((void**)&cur,  g_cur);
    cudaGetSymbolAddress((void**)&esrc, g_esrc);
    cudaGetSymbolAddress((void**)&eidx, g_eidx);
    cudaGetSymbolAddress((void**)&bsum, g_bsum);
    cudaGetSymbolAddress((void**)&dinv, g_dinv);
    cudaGetSymbolAddress((void**)&hl2,  g_hl2);
    cudaGetSymbolAddress((void**)&h2,   g_h2);
    cudaGetSymbolAddress((void**)&ab2,  g_ab2);
    cudaGetSymbolAddress((void**)&w1h,  g_w1h);
    cudaGetSymbolAddress((void**)&w2h,  g_w2h);
    cudaGetSymbolAddress((void**)&wabh, g_wabh);

    const int T = 256;
    int NB = (n + 255) / 256;

    // fork: CSR build + weight conversions on side stream
    cudaMemsetAsync(cnt, 0, (size_t)n * sizeof(int), 0);
    cudaEventRecord(g_evFork, 0);
    cudaStreamWaitEvent(g_s2, g_evFork, 0);
    count_in<<<(E + T - 1) / T, T, 0, g_s2>>>(col, cnt, E);
    scan1<<<NB, T, 0, g_s2>>>(cnt, off, bsum, dinv, n);
    cudaEventRecord(g_evDinv, g_s2);
    scan2<<<1, 512, 0, g_s2>>>(bsum, NB);
    scan3<<<NB, T, 0, g_s2>>>(off, bsum, cur, n, E);
    fill_csr<<<(E + T - 1) / T, T, 0, g_s2>>>(row, col, cur, esrc, eidx, E);
    conv_w<<<(HIDD * HIDD + T - 1) / T, T, 0, g_s2>>>(W2, w2h, HIDD * HIDD);
    repack_wab_h<<<(64 * 128 + T - 1) / T, T, 0, g_s2>>>(l1W, wabh);
    cudaEventRecord(g_evJoin, g_s2);

    // main: W1 conversion overlaps count_in; gemm1 (scaled) waits only for dinv
    conv_w<<<(FIN * HIDD + T - 1) / T, T>>>(W1, w1h, FIN * HIDD);
    cudaStreamWaitEvent(0, g_evDinv, 0);
    gemm_mma<128, 64, true, false><<<(n + 63) / 64, 128>>>(x, w1h, dinv, hl2, n);
    cudaStreamWaitEvent(0, g_evJoin, 0);

    gather_agg<<<(n * 8 + T - 1) / T, T>>>(off, esrc, hl2, dinv, b1, h2, n);

    gemm_mma<64, 64, true, true><<<(n + 63) / 64, 128>>>(h2, w2h, dinv, hl2, n);
    gather_agg<<<(n * 8 + T - 1) / T, T>>>(off, esrc, hl2, dinv, b2, h2, n);

    gemm_mma<64, 128, false, true><<<(n + 63) / 64, 128>>>(h2, wabh, nullptr, ab2, n);
    edge_mlp_csc<<<(n * 8 + T - 1) / T, T>>>(off, esrc, eidx, ab2, l1b, l2W, l2b, out, n);
}